// round 2
// baseline (speedup 1.0000x reference)
#include <cuda_runtime.h>
#include <math.h>

// Problem constants
#define Ndim 32
#define Cdim 512
#define Tdim 1024
#define NT   32768            // N*T rows
#define NB   2048             // codes
#define CT   (Cdim*Tdim)      // 524288
#define XSZ  (Ndim*Cdim*Tdim) // 16777216

// Output packing (flattened tuple, in reference return order)
#define OFF_XD   0
#define OFF_LOSS 16777216
#define OFF_PERP 16777217
#define OFF_CB   16777218
#define OFF_CSE  (OFF_CB + NB*Cdim)   // 17825794
#define OFF_CNT  (OFF_CSE + NB*Cdim)  // 18874370

// Scratch (no cudaMalloc allowed)
__device__ __align__(16) float g_cc[NB];
__device__ __align__(16) int   g_idx[NT];
__device__ __align__(16) float g_nsum[NB*Cdim];
__device__ __align__(16) float g_ncnt[NB];
__device__ float g_loss;

// ---------------- packed f32x2 helpers (Blackwell FFMA2 path) ----------------
__device__ __forceinline__ unsigned long long pack2dup(float a) {
    unsigned long long r;
    asm("mov.b64 %0, {%1, %2};" : "=l"(r) : "f"(a), "f"(a));
    return r;
}
__device__ __forceinline__ void fma2(unsigned long long& d, unsigned long long a, unsigned long long b) {
    asm("fma.rn.f32x2 %0, %1, %2, %0;" : "+l"(d) : "l"(a), "l"(b));
}
__device__ __forceinline__ void unpack2(unsigned long long v, float& lo, float& hi) {
    asm("mov.b64 {%0, %1}, %2;" : "=f"(lo), "=f"(hi) : "l"(v));
}

// ---------------- 0: zero scratch ----------------
__global__ void zero_kernel() {
    int i = blockIdx.x * 256 + threadIdx.x;
    if (i < NB * Cdim) g_nsum[i] = 0.0f;
    if (i < NB)        g_ncnt[i] = 0.0f;
    if (i == 0)        g_loss = 0.0f;
}

// ---------------- 1: codebook squared norms ----------------
__global__ void norms_kernel(const float* __restrict__ cb) {
    int warp = threadIdx.x >> 5, lane = threadIdx.x & 31;
    int code = blockIdx.x * 8 + warp;
    const float* row = cb + (size_t)code * Cdim;
    float s = 0.0f;
    for (int j = lane; j < Cdim; j += 32) { float v = row[j]; s += v * v; }
    #pragma unroll
    for (int o = 16; o > 0; o >>= 1) s += __shfl_xor_sync(0xffffffffu, s, o);
    if (lane == 0) g_cc[code] = s;
}

// ---------------- 2: fused distance GEMM + argmin ----------------
// Block: 128 rows x all 2048 codes (in 128-code tiles), K=512 in 32-chunks.
// 256 threads, each owns an 8x8 micro-tile; FFMA2 packed accumulators.
__global__ __launch_bounds__(256) void argmin_kernel(const float* __restrict__ x,
                                                     const float* __restrict__ cb) {
    __shared__ __align__(16) float xs[32][128];   // xs[k][row]
    __shared__ __align__(16) float cs[32][132];   // cs[k][code], padded

    int tid = threadIdx.x;
    int tx = tid & 15, ty = tid >> 4;
    int r0 = blockIdx.x * 128;                    // 128 rows, same n (T=1024 % 128 == 0)
    const float* xbase = x + (size_t)(r0 >> 10) * CT + (r0 & 1023);

    float bestv[8]; int besti[8];
    #pragma unroll
    for (int i = 0; i < 8; i++) { bestv[i] = 3.0e38f; besti[i] = 0; }

    for (int nt = 0; nt < NB; nt += 128) {
        unsigned long long acc[8][4];
        #pragma unroll
        for (int i = 0; i < 8; i++)
            #pragma unroll
            for (int j = 0; j < 4; j++) acc[i][j] = 0ull;

        for (int k0 = 0; k0 < Cdim; k0 += 32) {
            // load X tile: coalesced, already [k][row] in global (row = t fastest)
            #pragma unroll
            for (int it = 0; it < 4; it++) {
                int idx = tid + it * 256;         // 0..1023 float4s
                int kk = idx >> 5;
                int r4 = (idx & 31) << 2;
                *(float4*)&xs[kk][r4] =
                    *(const float4*)(xbase + (size_t)(k0 + kk) * Tdim + r4);
            }
            // load CB tile with transpose into cs[k][code]
            #pragma unroll
            for (int it = 0; it < 4; it++) {
                int idx = tid + it * 256;
                int code = idx >> 3;              // 8 float4 per code row (32 k)
                int kp = (idx & 7) << 2;
                float4 v = *(const float4*)(cb + (size_t)(nt + code) * Cdim + k0 + kp);
                cs[kp + 0][code] = v.x; cs[kp + 1][code] = v.y;
                cs[kp + 2][code] = v.z; cs[kp + 3][code] = v.w;
            }
            __syncthreads();
            #pragma unroll
            for (int k = 0; k < 32; k++) {
                float4 a0 = *(float4*)&xs[k][ty * 8];
                float4 a1 = *(float4*)&xs[k][ty * 8 + 4];
                ulonglong2 bA = *(ulonglong2*)&cs[k][tx * 8];
                ulonglong2 bB = *(ulonglong2*)&cs[k][tx * 8 + 4];
                float av[8] = {a0.x, a0.y, a0.z, a0.w, a1.x, a1.y, a1.z, a1.w};
                #pragma unroll
                for (int i = 0; i < 8; i++) {
                    unsigned long long aa = pack2dup(av[i]);
                    fma2(acc[i][0], aa, bA.x);
                    fma2(acc[i][1], aa, bA.y);
                    fma2(acc[i][2], aa, bB.x);
                    fma2(acc[i][3], aa, bB.y);
                }
            }
            __syncthreads();
        }
        // epilogue for this 128-code tile: d = |c|^2 - 2*dot; track argmin
        float ccv[8];
        #pragma unroll
        for (int jj = 0; jj < 8; jj++) ccv[jj] = g_cc[nt + tx * 8 + jj];
        #pragma unroll
        for (int i = 0; i < 8; i++) {
            #pragma unroll
            for (int jp = 0; jp < 4; jp++) {
                float lo, hi; unpack2(acc[i][jp], lo, hi);
                float d0 = ccv[jp * 2]     - 2.0f * lo;
                float d1 = ccv[jp * 2 + 1] - 2.0f * hi;
                int g0 = nt + tx * 8 + jp * 2;
                if (d0 < bestv[i]) { bestv[i] = d0; besti[i] = g0; }
                if (d1 < bestv[i]) { bestv[i] = d1; besti[i] = g0 + 1; }
            }
        }
    }
    // cross-thread (tx) reduction per row; reuse xs as scratch
    float* red_v = &xs[0][0];                 // 2048 floats
    int*   red_i = (int*)(&xs[0][0]) + 2048;  // 2048 ints
    __syncthreads();
    #pragma unroll
    for (int i = 0; i < 8; i++) {
        red_v[(ty * 8 + i) * 16 + tx] = bestv[i];
        red_i[(ty * 8 + i) * 16 + tx] = besti[i];
    }
    __syncthreads();
    if (tid < 128) {
        float bv = red_v[tid * 16]; int bi = red_i[tid * 16];
        for (int t = 1; t < 16; t++) {
            float v = red_v[tid * 16 + t]; int ix = red_i[tid * 16 + t];
            if (v < bv || (v == bv && ix < bi)) { bv = v; bi = ix; }
        }
        g_idx[r0 + tid] = bi;
    }
}

// ---------------- 3: code counts ----------------
__global__ void count_kernel() {
    int r = blockIdx.x * 256 + threadIdx.x;
    if (r < NT) atomicAdd(&g_ncnt[g_idx[r]], 1.0f);
}

// ---------------- 4: segment sum scatter (4 t-values per thread) ----------------
__global__ void scatter_kernel(const float* __restrict__ x) {
    int gi = (blockIdx.x * 256 + threadIdx.x) << 2;   // element index in [n][c][t]
    int n = gi >> 19;
    int rem = gi & (CT - 1);
    int c = rem >> 10;
    int t = rem & 1023;
    int row = (n << 10) + t;
    float4 xv = *(const float4*)(x + gi);
    int4 idx = *(const int4*)(g_idx + row);
    atomicAdd(&g_nsum[idx.x * Cdim + c], xv.x);
    atomicAdd(&g_nsum[idx.y * Cdim + c], xv.y);
    atomicAdd(&g_nsum[idx.z * Cdim + c], xv.z);
    atomicAdd(&g_nsum[idx.w * Cdim + c], xv.w);
}

// ---------------- 5: x_d output + commit-loss partial ----------------
__global__ void out_kernel(const float* __restrict__ x, const float* __restrict__ cb,
                           float* __restrict__ out) {
    int gi = (blockIdx.x * 256 + threadIdx.x) << 2;
    int n = gi >> 19;
    int rem = gi & (CT - 1);
    int c = rem >> 10;
    int t = rem & 1023;
    int row = (n << 10) + t;
    float4 xv = *(const float4*)(x + gi);
    int4 idx = *(const int4*)(g_idx + row);
    float4 o;
    o.x = cb[(size_t)idx.x * Cdim + c];
    o.y = cb[(size_t)idx.y * Cdim + c];
    o.z = cb[(size_t)idx.z * Cdim + c];
    o.w = cb[(size_t)idx.w * Cdim + c];
    *(float4*)(out + OFF_XD + gi) = o;
    float dx = xv.x - o.x, dy = xv.y - o.y, dz = xv.z - o.z, dw = xv.w - o.w;
    float s = dx * dx + dy * dy + dz * dz + dw * dw;
    #pragma unroll
    for (int off = 16; off > 0; off >>= 1) s += __shfl_xor_sync(0xffffffffu, s, off);
    __shared__ float sh[8];
    int lane = threadIdx.x & 31, w = threadIdx.x >> 5;
    if (lane == 0) sh[w] = s;
    __syncthreads();
    if (threadIdx.x == 0) {
        float tot = 0.0f;
        #pragma unroll
        for (int i = 0; i < 8; i++) tot += sh[i];
        atomicAdd(&g_loss, tot);
    }
}

// ---------------- 6: EMA update + codebook reset + count out ----------------
__global__ void ema_kernel(const float* __restrict__ x,
                           const float* __restrict__ code_sum,
                           const float* __restrict__ code_count,
                           float* __restrict__ out) {
    int gi = blockIdx.x * 256 + threadIdx.x;  // 0..NB*C-1
    int code = gi >> 9;
    int c = gi & 511;
    float cse = 0.99f * code_sum[gi] + 0.01f * g_nsum[gi];
    float cnt = 0.99f * code_count[code] + 0.01f * g_ncnt[code];
    out[OFF_CSE + gi] = cse;
    float ncb;
    if (cnt >= 1.0f) {
        ncb = cse / fmaxf(cnt, 1e-10f);
    } else {
        // out_random = x_flat[code] : n = code/1024, t = code%1024
        int t = code & 1023;
        int n = code >> 10;
        ncb = x[(size_t)n * CT + (size_t)c * Tdim + t];
    }
    out[OFF_CB + gi] = ncb;
    if (c == 0) out[OFF_CNT + code] = cnt;
}

// ---------------- 7: perplexity + loss finalize ----------------
__global__ void finalize_kernel(float* __restrict__ out) {
    float h = 0.0f;
    for (int code = threadIdx.x; code < NB; code += 256) {
        float p = g_ncnt[code] * (1.0f / 32768.0f);
        h += p * logf(p + 1e-7f);
    }
    #pragma unroll
    for (int off = 16; off > 0; off >>= 1) h += __shfl_xor_sync(0xffffffffu, h, off);
    __shared__ float sh[8];
    int lane = threadIdx.x & 31, w = threadIdx.x >> 5;
    if (lane == 0) sh[w] = h;
    __syncthreads();
    if (threadIdx.x == 0) {
        float tot = 0.0f;
        #pragma unroll
        for (int i = 0; i < 8; i++) tot += sh[i];
        out[OFF_PERP] = expf(-tot);
        out[OFF_LOSS] = g_loss * (1.0f / (float)XSZ);
    }
}

extern "C" void kernel_launch(void* const* d_in, const int* in_sizes, int n_in,
                              void* d_out, int out_size) {
    const float* x    = (const float*)d_in[0];
    const float* cb   = (const float*)d_in[1];
    const float* csum = (const float*)d_in[2];
    const float* ccnt = (const float*)d_in[3];
    float* out = (float*)d_out;

    zero_kernel    <<<(NB * Cdim + 255) / 256, 256>>>();
    norms_kernel   <<<NB / 8, 256>>>(cb);
    argmin_kernel  <<<NT / 128, 256>>>(x, cb);
    count_kernel   <<<NT / 256, 256>>>();
    scatter_kernel <<<XSZ / 4 / 256, 256>>>(x);
    out_kernel     <<<XSZ / 4 / 256, 256>>>(x, cb, out);
    ema_kernel     <<<NB * Cdim / 256, 256>>>(x, csum, ccnt, out);
    finalize_kernel<<<1, 256>>>(out);
}

// round 5
// speedup vs baseline: 1.8823x; 1.8823x over previous
#include <cuda_runtime.h>
#include <math.h>
#include <cstdint>

#define Ndim 32
#define Cdim 512
#define Tdim 1024
#define NT   32768
#define NB   2048
#define CT   (Cdim*Tdim)
#define XSZ  (Ndim*Cdim*Tdim)

#define OFF_XD   0
#define OFF_LOSS 16777216
#define OFF_PERP 16777217
#define OFF_CB   16777218
#define OFF_CSE  (OFF_CB + NB*Cdim)
#define OFF_CNT  (OFF_CSE + NB*Cdim)

// Scratch (device globals: the sanctioned no-cudaMalloc path)
__device__ __align__(16) float g_cc[NB];
__device__ __align__(16) int   g_idx[NT];
__device__ __align__(16) float g_nsum[NB*Cdim];
__device__ __align__(16) float g_ncnt[NB];
__device__ float g_loss;
__device__ __align__(16) float g_dhat[(size_t)NT * NB];   // 256 MB approx distances
__device__ __align__(16) float g_xT[(size_t)NT * Cdim];   // 64 MB x transposed [row][c]

// ---------------------------------------------------------------- helpers
__device__ __forceinline__ void cp_async16(uint32_t saddr, const void* g) {
    asm volatile("cp.async.ca.shared.global [%0], [%1], 16;" :: "r"(saddr), "l"(g));
}
__device__ __forceinline__ void cp_commit() {
    asm volatile("cp.async.commit_group;" ::: "memory");
}
__device__ __forceinline__ void mma_tf32(float* d, const uint32_t* a, const uint32_t* b) {
    asm volatile(
        "mma.sync.aligned.m16n8k8.row.col.f32.tf32.tf32.f32 "
        "{%0,%1,%2,%3}, {%4,%5,%6,%7}, {%8,%9}, {%0,%1,%2,%3};"
        : "+f"(d[0]), "+f"(d[1]), "+f"(d[2]), "+f"(d[3])
        : "r"(a[0]), "r"(a[1]), "r"(a[2]), "r"(a[3]), "r"(b[0]), "r"(b[1]));
}

// ---------------- 0: zero scratch ----------------
__global__ void zero_kernel() {
    int i = blockIdx.x * 256 + threadIdx.x;
    if (i < NB * Cdim) g_nsum[i] = 0.0f;
    if (i < NB)        g_ncnt[i] = 0.0f;
    if (i == 0)        g_loss = 0.0f;
}

// ---------------- 1: codebook squared norms ----------------
__global__ void norms_kernel(const float* __restrict__ cb) {
    int warp = threadIdx.x >> 5, lane = threadIdx.x & 31;
    int code = blockIdx.x * 8 + warp;
    const float* row = cb + (size_t)code * Cdim;
    float s = 0.0f;
    for (int j = lane; j < Cdim; j += 32) { float v = row[j]; s += v * v; }
    #pragma unroll
    for (int o = 16; o > 0; o >>= 1) s += __shfl_xor_sync(0xffffffffu, s, o);
    if (lane == 0) g_cc[code] = s;
}

// ---------------- 2: transpose x -> xT[row][c] ----------------
__global__ void transpose_kernel(const float* __restrict__ x) {
    __shared__ float s[32][33];
    int b = blockIdx.x;
    int ct = b & 15;          // c tile (16)
    int tt = (b >> 4) & 31;   // t tile (32)
    int n  = b >> 9;          // batch (32)
    int tid = threadIdx.x;
    int l5 = tid & 31, h3 = tid >> 5;
    #pragma unroll
    for (int q = 0; q < 4; q++) {
        int c_l = h3 + q * 8;
        s[c_l][l5] = x[(size_t)n * CT + (size_t)(ct * 32 + c_l) * Tdim + tt * 32 + l5];
    }
    __syncthreads();
    #pragma unroll
    for (int q = 0; q < 4; q++) {
        int t_l = h3 + q * 8;
        g_xT[(size_t)(n * 1024 + tt * 32 + t_l) * Cdim + ct * 32 + l5] = s[l5][t_l];
    }
}

// ---------------- 3: TF32 mma.sync screen GEMM -> d_hat ----------------
// BM=128 rows x all 2048 codes (16 n-tiles of 128), BK=32, double-buffered cp.async.
#define BM 128
#define BN 128
#define BK 32
#define AS_STRIDE 136
#define BS_STRIDE 36
#define AS_FLOATS (BK * AS_STRIDE)                 // 4352
#define BS_FLOATS (BN * BS_STRIDE)                 // 4608
#define SMEM_BYTES ((2*AS_FLOATS + 2*BS_FLOATS)*4) // 71680

__global__ __launch_bounds__(256, 2) void gemm_dhat(const float* __restrict__ x,
                                                    const float* __restrict__ cb) {
    extern __shared__ float sm[];
    float* As[2] = { sm, sm + AS_FLOATS };
    float* Bs[2] = { sm + 2*AS_FLOATS, sm + 2*AS_FLOATS + BS_FLOATS };
    uint32_t smbase = (uint32_t)__cvta_generic_to_shared(sm);
    uint32_t smA[2] = { smbase, smbase + AS_FLOATS*4u };
    uint32_t smB[2] = { smbase + 2u*AS_FLOATS*4u, smbase + (2u*AS_FLOATS + BS_FLOATS)*4u };

    int tid = threadIdx.x, lane = tid & 31, wid = tid >> 5;
    int wm = wid >> 2, wn = wid & 3;       // warp grid 2 (m) x 4 (n)
    int lq = lane & 3, lr = lane >> 2;
    int r0 = blockIdx.x * BM;
    const float* xb = x + (size_t)(r0 >> 10) * CT + (r0 & 1023);

    int a_p  = (tid & 31) << 2;  // float offset within a k-row (0..124)
    int a_kb = tid >> 5;         // base k (0..7)
    int b_kp = (tid & 7) << 2;   // float offset within code row
    int b_cb = tid >> 3;         // base code (0..31)

    float acc[4][4][4];
    #pragma unroll
    for (int mi = 0; mi < 4; mi++)
        #pragma unroll
        for (int ni = 0; ni < 4; ni++)
            #pragma unroll
            for (int v = 0; v < 4; v++) acc[mi][ni][v] = 0.0f;

    auto load_tiles = [&](int buf, int nt, int kc) {
        #pragma unroll
        for (int it = 0; it < 4; it++) {
            int k = a_kb + it * 8;
            cp_async16(smA[buf] + (uint32_t)(k * AS_STRIDE + a_p) * 4u,
                       xb + (size_t)(kc + k) * Tdim + a_p);
        }
        #pragma unroll
        for (int it = 0; it < 4; it++) {
            int code = b_cb + it * 32;
            cp_async16(smB[buf] + (uint32_t)(code * BS_STRIDE + b_kp) * 4u,
                       cb + (size_t)(nt + code) * Cdim + kc + b_kp);
        }
        cp_commit();
    };

    load_tiles(0, 0, 0);

    for (int i = 0; i < 256; i++) {            // (nt, kc) flattened: 16 x 16
        int nxt = i + 1;
        if (nxt < 256) {
            load_tiles(nxt & 1, (nxt >> 4) * 128, (nxt & 15) * 32);
            asm volatile("cp.async.wait_group 1;" ::: "memory");
        } else {
            asm volatile("cp.async.wait_group 0;" ::: "memory");
        }
        __syncthreads();

        const float* A = As[i & 1];
        const float* B = Bs[i & 1];
        #pragma unroll
        for (int kk = 0; kk < 4; kk++) {
            uint32_t a[4][4], b[4][2];
            #pragma unroll
            for (int mi = 0; mi < 4; mi++) {
                const float* ap = A + (kk * 8 + lq) * AS_STRIDE + wm * 64 + mi * 16 + lr;
                a[mi][0] = __float_as_uint(ap[0]);
                a[mi][1] = __float_as_uint(ap[8]);
                a[mi][2] = __float_as_uint(ap[4 * AS_STRIDE]);
                a[mi][3] = __float_as_uint(ap[4 * AS_STRIDE + 8]);
            }
            #pragma unroll
            for (int ni = 0; ni < 4; ni++) {
                const float* bp = B + (wn * 32 + ni * 8 + lr) * BS_STRIDE + kk * 8 + lq;
                b[ni][0] = __float_as_uint(bp[0]);
                b[ni][1] = __float_as_uint(bp[4]);
            }
            #pragma unroll
            for (int mi = 0; mi < 4; mi++)
                #pragma unroll
                for (int ni = 0; ni < 4; ni++)
                    mma_tf32(acc[mi][ni], a[mi], b[ni]);
        }

        if ((i & 15) == 15) {  // end of K for this n-tile: spill d_hat, reset accs
            int nt = (i >> 4) * 128;
            #pragma unroll
            for (int mi = 0; mi < 4; mi++) {
                int row = r0 + wm * 64 + mi * 16 + lr;
                #pragma unroll
                for (int ni = 0; ni < 4; ni++) {
                    int col = nt + wn * 32 + ni * 8 + 2 * lq;
                    float cc0 = __ldg(&g_cc[col]);
                    float cc1 = __ldg(&g_cc[col + 1]);
                    float2 v0 = make_float2(cc0 - 2.0f * acc[mi][ni][0],
                                            cc1 - 2.0f * acc[mi][ni][1]);
                    float2 v1 = make_float2(cc0 - 2.0f * acc[mi][ni][2],
                                            cc1 - 2.0f * acc[mi][ni][3]);
                    *(float2*)&g_dhat[(size_t)row * NB + col] = v0;
                    *(float2*)&g_dhat[(size_t)(row + 8) * NB + col] = v1;
                    acc[mi][ni][0] = acc[mi][ni][1] = acc[mi][ni][2] = acc[mi][ni][3] = 0.0f;
                }
            }
        }
        __syncthreads();
    }
}

// ---------------- 4: rescue — exact fp32 argmin among margin candidates ----------------
// Margin 8.0 > 2*delta, delta <= 2^-9 * |x||c| (tf32 truncation worst case).
__global__ void rescue_kernel(const float* __restrict__ cb) {
    int wid = threadIdx.x >> 5, lane = threadIdx.x & 31;
    int row = blockIdx.x * 8 + wid;

    float xr[16];
    #pragma unroll
    for (int q = 0; q < 16; q++)
        xr[q] = g_xT[(size_t)row * Cdim + lane + q * 32];

    float dv[64];
    const float* drow = &g_dhat[(size_t)row * NB];
    #pragma unroll
    for (int i = 0; i < 64; i++) dv[i] = drow[lane + i * 32];

    float bv = dv[0];
    #pragma unroll
    for (int i = 1; i < 64; i++) bv = fminf(bv, dv[i]);
    #pragma unroll
    for (int o = 16; o > 0; o >>= 1) bv = fminf(bv, __shfl_xor_sync(0xffffffffu, bv, o));

    float thr = bv + 8.0f;
    float bestE = 3.0e38f;
    int   bestI = 0;
    #pragma unroll 4
    for (int i = 0; i < 64; i++) {
        unsigned mask = __ballot_sync(0xffffffffu, dv[i] <= thr);
        while (mask) {
            int s = __ffs(mask) - 1;
            mask &= mask - 1;
            int j = i * 32 + s;
            const float* crow = cb + (size_t)j * Cdim;
            float p = 0.0f;
            #pragma unroll
            for (int q = 0; q < 16; q++)
                p += xr[q] * __ldg(&crow[lane + q * 32]);
            #pragma unroll
            for (int o = 16; o > 0; o >>= 1) p += __shfl_xor_sync(0xffffffffu, p, o);
            float d = __ldg(&g_cc[j]) - 2.0f * p;
            if (d < bestE) { bestE = d; bestI = j; }   // ascending j => first-index ties
        }
    }
    if (lane == 0) g_idx[row] = bestI;
}

// ---------------- 5: segment sum scatter + counts ----------------
__global__ void scatter_kernel(const float* __restrict__ x) {
    int gi = (blockIdx.x * 256 + threadIdx.x) << 2;
    int n = gi >> 19;
    int rem = gi & (CT - 1);
    int c = rem >> 10;
    int t = rem & 1023;
    int row = (n << 10) + t;
    float4 xv = *(const float4*)(x + gi);
    int4 idx = *(const int4*)(g_idx + row);
    atomicAdd(&g_nsum[idx.x * Cdim + c], xv.x);
    atomicAdd(&g_nsum[idx.y * Cdim + c], xv.y);
    atomicAdd(&g_nsum[idx.z * Cdim + c], xv.z);
    atomicAdd(&g_nsum[idx.w * Cdim + c], xv.w);
    if (c == 0) {
        atomicAdd(&g_ncnt[idx.x], 1.0f);
        atomicAdd(&g_ncnt[idx.y], 1.0f);
        atomicAdd(&g_ncnt[idx.z], 1.0f);
        atomicAdd(&g_ncnt[idx.w], 1.0f);
    }
}

// ---------------- 6: x_d output + commit-loss partial ----------------
__global__ void out_kernel(const float* __restrict__ x, const float* __restrict__ cb,
                           float* __restrict__ out) {
    int gi = (blockIdx.x * 256 + threadIdx.x) << 2;
    int n = gi >> 19;
    int rem = gi & (CT - 1);
    int c = rem >> 10;
    int t = rem & 1023;
    int row = (n << 10) + t;
    float4 xv = *(const float4*)(x + gi);
    int4 idx = *(const int4*)(g_idx + row);
    float4 o;
    o.x = cb[(size_t)idx.x * Cdim + c];
    o.y = cb[(size_t)idx.y * Cdim + c];
    o.z = cb[(size_t)idx.z * Cdim + c];
    o.w = cb[(size_t)idx.w * Cdim + c];
    *(float4*)(out + OFF_XD + gi) = o;
    float dx = xv.x - o.x, dy = xv.y - o.y, dz = xv.z - o.z, dw = xv.w - o.w;
    float s = dx * dx + dy * dy + dz * dz + dw * dw;
    #pragma unroll
    for (int off = 16; off > 0; off >>= 1) s += __shfl_xor_sync(0xffffffffu, s, off);
    __shared__ float sh[8];
    int lane = threadIdx.x & 31, w = threadIdx.x >> 5;
    if (lane == 0) sh[w] = s;
    __syncthreads();
    if (threadIdx.x == 0) {
        float tot = 0.0f;
        #pragma unroll
        for (int i = 0; i < 8; i++) tot += sh[i];
        atomicAdd(&g_loss, tot);
    }
}

// ---------------- 7: EMA update + codebook reset + count out ----------------
__global__ void ema_kernel(const float* __restrict__ x,
                           const float* __restrict__ code_sum,
                           const float* __restrict__ code_count,
                           float* __restrict__ out) {
    int gi = blockIdx.x * 256 + threadIdx.x;
    int code = gi >> 9;
    int c = gi & 511;
    float cse = 0.99f * code_sum[gi] + 0.01f * g_nsum[gi];
    float cnt = 0.99f * code_count[code] + 0.01f * g_ncnt[code];
    out[OFF_CSE + gi] = cse;
    float ncb;
    if (cnt >= 1.0f) {
        ncb = cse / fmaxf(cnt, 1e-10f);
    } else {
        int t = code & 1023;
        int n = code >> 10;
        ncb = x[(size_t)n * CT + (size_t)c * Tdim + t];
    }
    out[OFF_CB + gi] = ncb;
    if (c == 0) out[OFF_CNT + code] = cnt;
}

// ---------------- 8: perplexity + loss finalize ----------------
__global__ void finalize_kernel(float* __restrict__ out) {
    float h = 0.0f;
    for (int code = threadIdx.x; code < NB; code += 256) {
        float p = g_ncnt[code] * (1.0f / 32768.0f);
        h += p * logf(p + 1e-7f);
    }
    #pragma unroll
    for (int off = 16; off > 0; off >>= 1) h += __shfl_xor_sync(0xffffffffu, h, off);
    __shared__ float sh[8];
    int lane = threadIdx.x & 31, w = threadIdx.x >> 5;
    if (lane == 0) sh[w] = h;
    __syncthreads();
    if (threadIdx.x == 0) {
        float tot = 0.0f;
        #pragma unroll
        for (int i = 0; i < 8; i++) tot += sh[i];
        out[OFF_PERP] = expf(-tot);
        out[OFF_LOSS] = g_loss * (1.0f / (float)XSZ);
    }
}

extern "C" void kernel_launch(void* const* d_in, const int* in_sizes, int n_in,
                              void* d_out, int out_size) {
    const float* x    = (const float*)d_in[0];
    const float* cb   = (const float*)d_in[1];
    const float* csum = (const float*)d_in[2];
    const float* ccnt = (const float*)d_in[3];
    float* out = (float*)d_out;

    cudaFuncSetAttribute(gemm_dhat, cudaFuncAttributeMaxDynamicSharedMemorySize, SMEM_BYTES);

    zero_kernel     <<<(NB * Cdim + 255) / 256, 256>>>();
    norms_kernel    <<<NB / 8, 256>>>(cb);
    transpose_kernel<<<Ndim * 32 * 16, 256>>>(x);
    gemm_dhat       <<<NT / BM, 256, SMEM_BYTES>>>(x, cb);
    rescue_kernel   <<<NT / 8, 256>>>(cb);
    scatter_kernel  <<<XSZ / 4 / 256, 256>>>(x);
    out_kernel      <<<XSZ / 4 / 256, 256>>>(x, cb, out);
    ema_kernel      <<<NB * Cdim / 256, 256>>>(x, csum, ccnt, out);
    finalize_kernel <<<1, 256>>>(out);
}